// round 15
// baseline (speedup 1.0000x reference)
#include <cuda_runtime.h>
#include <cuda_bf16.h>
#include <math.h>
#include <stdint.h>

#define HW 16384
#define PLN (128 * 136)          // padded plane elems per (b,ci)

// fp32 scratch (module-load allocated, legal per harness rules)
__device__ float g_om [4 * 216 * HW];
__device__ float g_em [4 *  72 * HW];

// Pre-split inputs: 3 kx-shifted zero-padded bf16 planes, hi & lo.
// layout [s][b*ci][h][136], row stride 272B (16B-aligned).
__device__ __nv_bfloat16 g_off_hi[3 * 4 * 64 * PLN];
__device__ __nv_bfloat16 g_off_lo[3 * 4 * 64 * PLN];
__device__ __nv_bfloat16 g_shf_hi[3 * 4 * 64 * PLN];
__device__ __nv_bfloat16 g_shf_lo[3 * 4 * 64 * PLN];
__device__ __nv_bfloat16 g_e1_hi [3 * 4 * 64 * PLN];
__device__ __nv_bfloat16 g_e1_lo [3 * 4 * 64 * PLN];

// Pre-split weights (separate hi/lo bf16, K-major [co][Cin*9])
__device__ __nv_bfloat16 g_wh_om [216 *  576];
__device__ __nv_bfloat16 g_wl_om [216 *  576];
__device__ __nv_bfloat16 g_wh_em1[ 64 * 1152];
__device__ __nv_bfloat16 g_wl_em1[ 64 * 1152];
__device__ __nv_bfloat16 g_wh_em2[ 72 *  576];
__device__ __nv_bfloat16 g_wl_em2[ 72 *  576];

// ---------------------------------------------------------------------------
__global__ void wsplit2_kernel(const float* __restrict__ w,
                               __nv_bfloat16* __restrict__ hi,
                               __nv_bfloat16* __restrict__ lo, int n)
{
    int i = blockIdx.x * 256 + threadIdx.x;
    if (i >= n) return;
    float x = w[i];
    __nv_bfloat16 h = __float2bfloat16(x);
    hi[i] = h;
    lo[i] = __float2bfloat16(x - __bfloat162float(h));
}

// presplit TWO inputs (off, shf) into 3 shifted padded bf16 hi/lo planes
__global__ void psplit2_kernel(const float* __restrict__ srcA,
                               __nv_bfloat16* __restrict__ hiA,
                               __nv_bfloat16* __restrict__ loA,
                               const float* __restrict__ srcB,
                               __nv_bfloat16* __restrict__ hiB,
                               __nv_bfloat16* __restrict__ loB)
{
    int h = blockIdx.x, bc = blockIdx.y, m = threadIdx.x;
    if (m >= 136) return;
    const float* src = srcA;
    __nv_bfloat16 *hi = hiA, *lo = loA;
    if (bc >= 256) { bc -= 256; src = srcB; hi = hiB; lo = loB; }
    const float* row = src + (size_t)bc * HW + h * 128;
    size_t S = (size_t)256 * PLN;
#pragma unroll
    for (int s = 0; s < 3; s++) {
        int g = m - 1 + s;
        float v = (g >= 0 && g < 128) ? row[g] : 0.f;
        __nv_bfloat16 hv = __float2bfloat16(v);
        __nv_bfloat16 lv = __float2bfloat16(v - __bfloat162float(hv));
        size_t o = (size_t)s * S + ((size_t)bc * 128 + h) * 136 + m;
        hi[o] = hv;
        lo[o] = lv;
    }
}

// ---------------------------------------------------------------------------
// warp-mma helpers (baseline PTX, valid at compute_103)
// ---------------------------------------------------------------------------
__device__ __forceinline__ void ldm_x4t(uint32_t* r, uint32_t addr) {
    asm volatile("ldmatrix.sync.aligned.m8n8.x4.trans.shared.b16 {%0,%1,%2,%3}, [%4];"
        : "=r"(r[0]), "=r"(r[1]), "=r"(r[2]), "=r"(r[3]) : "r"(addr));
}
__device__ __forceinline__ void ldm_x4n(uint32_t* r, uint32_t addr) {
    asm volatile("ldmatrix.sync.aligned.m8n8.x4.shared.b16 {%0,%1,%2,%3}, [%4];"
        : "=r"(r[0]), "=r"(r[1]), "=r"(r[2]), "=r"(r[3]) : "r"(addr));
}
__device__ __forceinline__ void ldm_x2(uint32_t* r, uint32_t addr) {
    asm volatile("ldmatrix.sync.aligned.m8n8.x2.shared.b16 {%0,%1}, [%2];"
        : "=r"(r[0]), "=r"(r[1]) : "r"(addr));
}
__device__ __forceinline__ void mma_bf16(float* c, const uint32_t* a, const uint32_t* b) {
    asm volatile("mma.sync.aligned.m16n8k16.row.col.f32.bf16.bf16.f32 "
        "{%0,%1,%2,%3},{%4,%5,%6,%7},{%8,%9},{%0,%1,%2,%3};"
        : "+f"(c[0]), "+f"(c[1]), "+f"(c[2]), "+f"(c[3])
        : "r"(a[0]), "r"(a[1]), "r"(a[2]), "r"(a[3]), "r"(b[0]), "r"(b[1]));
}

// ===========================================================================
// Implicit-GEMM conv3x3 on mma.sync bf16 3-pass, cp.async double-buffered.
// 512 threads; 16 warps = 8 M-tiles x 2 N-groups. A staged k-major (272B
// rows) via 16B cp.async from pre-split shifted planes; ldmatrix.x4.trans.
// B staged n-major (144B rows); paired ldmatrix.x4 loads two N-tiles at once.
// EPI: 0 = fp32 NCHW store, 1 = write bf16 hi/lo shifted planes (g_e1_*).
// ===========================================================================
template<int CIN, int CIN1, int COUT, int NTG0, int ACT, int EPI>
__global__ __launch_bounds__(512, 1) void conv_ps_kernel(
    const __nv_bfloat16* __restrict__ p1hi, const __nv_bfloat16* __restrict__ p1lo,
    const __nv_bfloat16* __restrict__ p2hi, const __nv_bfloat16* __restrict__ p2lo,
    const __nv_bfloat16* __restrict__ whi,  const __nv_bfloat16* __restrict__ wlo,
    const float* __restrict__ bias, float* __restrict__ out)
{
    constexpr int K      = CIN * 9;
    constexpr int NCH    = K / 64;
    constexpr int NT_TOT = (COUT + 7) / 8;
    constexpr int CIN2   = CIN - CIN1;
    constexpr size_t S1  = (size_t)4 * CIN1 * PLN;
    constexpr size_t S2  = (size_t)4 * (CIN2 ? CIN2 : 1) * PLN;
    constexpr int ASZ    = 2 * 64 * 272;
    constexpr int BB     = 2 * ASZ;
    constexpr int BSZ    = 2 * COUT * 144;

    extern __shared__ char smem[];
    uint32_t sb;
    asm("{ .reg .u64 t; cvta.to.shared.u64 t, %1; cvt.u32.u64 %0, t; }"
        : "=r"(sb) : "l"(smem));

    const int tid  = threadIdx.x;
    const int lane = tid & 31;
    const int wid  = tid >> 5;
    const int h    = blockIdx.x;
    const int b    = blockIdx.y;

    const int mw = wid & 7;
    const int wg = wid >> 3;
    const int m0 = mw * 16;
    const int ntc = wg ? (NT_TOT - NTG0) : NTG0;
    const int ntb = wg * NTG0;

    float acc[NTG0][4];
#pragma unroll
    for (int nt = 0; nt < NTG0; nt++)
#pragma unroll
        for (int q = 0; q < 4; q++) acc[nt][q] = 0.f;

    const uint32_t a_k  = (uint32_t)(((lane >> 4) << 3) + (lane & 7));
    const uint32_t a_m  = (uint32_t)(m0 + (((lane >> 3) & 1) << 3));
    const uint32_t aoff = a_k * 272 + a_m * 2;
    const uint32_t boff  = (uint32_t)((lane & 7) * 144 + ((lane >> 3) & 1) * 16);
    const uint32_t boff4 = (uint32_t)(((lane >> 4) & 1) * 1152
                                    + (lane & 7) * 144 + ((lane >> 3) & 1) * 16);

    auto stage = [&](int kc, int buf) {
#pragma unroll
        for (int i = 0; i < 4; i++) {
            int idx = tid + 512 * i;
            int pl  = idx >> 10;
            int rem = idx & 1023;
            int kr  = rem >> 4;
            int ch  = rem & 15;
            int k  = kc * 64 + kr;
            int ci = k / 9, r = k - 9 * ci, ky = r / 3, kx = r - 3 * ky;
            int gh = h - 1 + ky;
            int sz = ((unsigned)gh < 128u) ? 16 : 0;
            int ghc = min(max(gh, 0), 127);
            const __nv_bfloat16* base;
            if (ci < CIN1)
                base = (pl ? p1lo : p1hi) + (size_t)kx * S1
                     + ((size_t)(b * CIN1 + ci) * 128 + ghc) * 136;
            else
                base = (pl ? p2lo : p2hi) + (size_t)kx * S2
                     + ((size_t)(b * CIN2 + (ci - CIN1)) * 128 + ghc) * 136;
            const char* src = (const char*)base + ch * 16;
            uint32_t dst = sb + buf * ASZ + pl * 17408 + kr * 272 + ch * 16;
            asm volatile("cp.async.cg.shared.global [%0], [%1], 16, %2;"
                         :: "r"(dst), "l"(src), "r"(sz));
        }
        for (int idx = tid; idx < COUT * 16; idx += 512) {
            int pl  = (idx >= COUT * 8) ? 1 : 0;
            int rem = idx - pl * COUT * 8;
            int co  = rem >> 3;
            int ch  = rem & 7;
            const __nv_bfloat16* w = pl ? wlo : whi;
            const char* src = (const char*)(w + (size_t)co * K + kc * 64) + ch * 16;
            uint32_t dst = sb + BB + buf * BSZ + pl * (COUT * 144) + co * 144 + ch * 16;
            asm volatile("cp.async.cg.shared.global [%0], [%1], 16, 16;"
                         :: "r"(dst), "l"(src));
        }
        asm volatile("cp.async.commit_group;" ::: "memory");
    };

    stage(0, 0);

    int buf = 0;
    for (int kc = 0; kc < NCH; kc++, buf ^= 1) {
        if (kc + 1 < NCH) {
            stage(kc + 1, buf ^ 1);
            asm volatile("cp.async.wait_group 1;" ::: "memory");
        } else {
            asm volatile("cp.async.wait_group 0;" ::: "memory");
        }
        __syncthreads();

        uint32_t Ab = sb + buf * ASZ;
        uint32_t Bb = sb + BB + buf * BSZ;
#pragma unroll
        for (int kt = 0; kt < 4; kt++) {
            uint32_t ah[4], al[4];
            ldm_x4t(ah, Ab + kt * 4352 + aoff);
            ldm_x4t(al, Ab + 17408 + kt * 4352 + aoff);
#pragma unroll
            for (int nt = 0; nt < NTG0; nt += 2) {
                if (nt + 1 < ntc) {
                    // paired x4: lanes 0-15 -> nt, 16-31 -> nt+1
                    uint32_t bh[4], bl[4];
                    ldm_x4n(bh, Bb + (ntb + nt) * 1152 + boff4 + kt * 32);
                    ldm_x4n(bl, Bb + COUT * 144 + (ntb + nt) * 1152 + boff4 + kt * 32);
                    mma_bf16(acc[nt],     ah, bh);
                    mma_bf16(acc[nt],     ah, bl);
                    mma_bf16(acc[nt],     al, bh);
                    mma_bf16(acc[nt + 1], ah, bh + 2);
                    mma_bf16(acc[nt + 1], ah, bl + 2);
                    mma_bf16(acc[nt + 1], al, bh + 2);
                } else if (nt < ntc) {
                    uint32_t bh[2], bl[2];
                    ldm_x2(bh, Bb + (ntb + nt) * 1152 + boff + kt * 32);
                    ldm_x2(bl, Bb + COUT * 144 + (ntb + nt) * 1152 + boff + kt * 32);
                    mma_bf16(acc[nt], ah, bh);
                    mma_bf16(acc[nt], ah, bl);
                    mma_bf16(acc[nt], al, bh);
                }
            }
        }
        __syncthreads();
    }

    // ---- epilogue ----
    const int mA = m0 + (lane >> 2);
#pragma unroll
    for (int nt = 0; nt < NTG0; nt++) {
        if (nt < ntc) {
            int coA = (ntb + nt) * 8 + 2 * (lane & 3);
            float ba = bias[coA], bb = bias[coA + 1];
            float v[4] = { acc[nt][0] + ba, acc[nt][1] + bb,
                           acc[nt][2] + ba, acc[nt][3] + bb };
#pragma unroll
            for (int q = 0; q < 4; q++) {
                if (ACT == 1) v[q] = (v[q] >= 0.f) ? v[q] : 0.1f * v[q];
                if (ACT == 2) v[q] = 1.f / (1.f + expf(-v[q]));
            }
            if (EPI == 0) {
                size_t o00 = ((size_t)b * COUT + coA) * HW + h * 128 + mA;
                out[o00]          = v[0];
                out[o00 + HW]     = v[1];
                out[o00 + 8]      = v[2];
                out[o00 + HW + 8] = v[3];
            } else {
                // write 3 kx-shifted bf16 hi/lo plane cells for em2 staging
                constexpr size_t S = (size_t)4 * 64 * PLN;
#pragma unroll
                for (int q = 0; q < 4; q++) {
                    int c = coA + (q & 1);
                    int m = mA + (q >> 1) * 8;
                    __nv_bfloat16 hv = __float2bfloat16(v[q]);
                    __nv_bfloat16 lv = __float2bfloat16(v[q] - __bfloat162float(hv));
                    size_t rowb = ((size_t)(b * 64 + c) * 128 + h) * 136;
#pragma unroll
                    for (int s = 0; s < 3; s++) {
                        int j = m + 1 - s;
                        if (j >= 0) {
                            g_e1_hi[(size_t)s * S + rowb + j] = hv;
                            g_e1_lo[(size_t)s * S + rowb + j] = lv;
                        }
                    }
                }
            }
        }
    }
    // zero the unwritten horizontal border cells of the e1 planes
    if (EPI == 1 && mw == 0) {
        constexpr size_t S = (size_t)4 * 64 * PLN;
        int nch = ntc * 8;
        __nv_bfloat16 z = __float2bfloat16(0.f);
        for (int t = lane; t < nch * 25; t += 32) {
            int c = ntb * 8 + t / 25;
            int cell = t % 25;
            int s, j;
            if (cell == 0)       { s = 0; j = 0; }
            else if (cell < 8)   { s = 0; j = 128 + cell; }   // 129..135
            else if (cell < 16)  { s = 1; j = 120 + cell; }   // 128..135
            else                 { s = 2; j = 111 + cell; }   // 127..135
            size_t idx = (size_t)s * S + ((size_t)(b * 64 + c) * 128 + h) * 136 + j;
            g_e1_hi[idx] = z;
            g_e1_lo[idx] = z;
        }
    }
}

// ---------------------------------------------------------------------------
// Fused dual modulated deformable conv (DCNv2), stride 1, pad 1. (unchanged)
// ---------------------------------------------------------------------------
__global__ __launch_bounds__(256) void deform_kernel(
    const float* __restrict__ x, const float* __restrict__ s,
    const float* __restrict__ w_dc, const float* __restrict__ b_dc,
    float* __restrict__ out)
{
    __shared__ float s_w[8][8][9];

    const int tid = threadIdx.x;
    const int b = blockIdx.z >> 3;
    const int g = blockIdx.z & 7;
    const int ty = tid >> 4;
    const int tx = tid & 15;
    const int h  = blockIdx.y * 16 + ty;
    const int wp = blockIdx.x * 16 + tx;

    for (int i = tid; i < 576; i += 256)
        ((float*)s_w)[i] = w_dc[(size_t)g * 576 + i];
    __syncthreads();

    const int pix = h * 128 + wp;
    const float* om_b = g_om + (size_t)b * 216 * HW;
    const float* em_b = g_em + (size_t)b * 72 * HW;
    const float* xb = x + ((size_t)b * 64 + g * 8) * HW;
    const float* sb = s + ((size_t)b * 64 + g * 8) * HW;

    float accx[8], accs[8];
#pragma unroll
    for (int o = 0; o < 8; o++) { accx[o] = 0.f; accs[o] = 0.f; }

    for (int kk = 0; kk < 9; kk++) {
        const int mch = g * 9 + kk;
        float dy   = om_b[(size_t)(2 * mch) * HW + pix];
        float dx   = om_b[(size_t)(2 * mch + 1) * HW + pix];
        float mraw = om_b[(size_t)(144 + mch) * HW + pix];
        float mx = 1.f / (1.f + expf(-mraw));
        float me = em_b[(size_t)mch * HW + pix];

        float py = (float)(h - 1 + kk / 3) + dy;
        float px = (float)(wp - 1 + kk % 3) + dx;
        float y0f = floorf(py), x0f = floorf(px);
        int y0 = (int)y0f, x0 = (int)x0f;
        float ly = py - y0f, lx = px - x0f;
        int y1 = y0 + 1, x1 = x0 + 1;

        float vy0 = (y0 >= 0 && y0 < 128) ? 1.f : 0.f;
        float vy1 = (y1 >= 0 && y1 < 128) ? 1.f : 0.f;
        float vx0 = (x0 >= 0 && x0 < 128) ? 1.f : 0.f;
        float vx1 = (x1 >= 0 && x1 < 128) ? 1.f : 0.f;

        float w00 = (1.f - ly) * (1.f - lx) * vy0 * vx0;
        float w01 = (1.f - ly) * lx         * vy0 * vx1;
        float w10 = ly * (1.f - lx)         * vy1 * vx0;
        float w11 = ly * lx                 * vy1 * vx1;

        int cy0 = min(max(y0, 0), 127), cy1 = min(max(y1, 0), 127);
        int cx0 = min(max(x0, 0), 127), cx1 = min(max(x1, 0), 127);
        int i00 = cy0 * 128 + cx0, i01 = cy0 * 128 + cx1;
        int i10 = cy1 * 128 + cx0, i11 = cy1 * 128 + cx1;

#pragma unroll
        for (int c = 0; c < 8; c++) {
            const float* xp = xb + (size_t)c * HW;
            const float* sp = sb + (size_t)c * HW;
            float vx = w00 * xp[i00] + w01 * xp[i01] + w10 * xp[i10] + w11 * xp[i11];
            float vs = w00 * sp[i00] + w01 * sp[i01] + w10 * sp[i10] + w11 * sp[i11];
            float ax  = vx * mx;
            float as_ = vs * me;
#pragma unroll
            for (int o = 0; o < 8; o++) {
                float wv = s_w[o][c][kk];
                accx[o] += ax * wv;
                accs[o] += as_ * wv;
            }
        }
    }

#pragma unroll
    for (int o = 0; o < 8; o++) {
        float bs = b_dc[g * 8 + o];
        size_t oidx = ((size_t)b * 64 + g * 8 + o) * HW + pix;
        out[oidx] = accx[o] + bs;
        out[(size_t)4 * 64 * HW + oidx] = accs[o] + bs;
    }
}

extern "C" void kernel_launch(void* const* d_in, const int* in_sizes, int n_in,
                              void* d_out, int out_size)
{
    const float* x     = (const float*)d_in[0];
    const float* shf   = (const float*)d_in[1];
    const float* off   = (const float*)d_in[2];
    const float* w_om  = (const float*)d_in[3];
    const float* b_om  = (const float*)d_in[4];
    const float* w_em1 = (const float*)d_in[5];
    const float* b_em1 = (const float*)d_in[6];
    const float* w_em2 = (const float*)d_in[7];
    const float* b_em2 = (const float*)d_in[8];
    const float* w_dc  = (const float*)d_in[9];
    const float* b_dc  = (const float*)d_in[10];
    float* out = (float*)d_out;

    float *p_om, *p_em;
    cudaGetSymbolAddress((void**)&p_om,  g_om);
    cudaGetSymbolAddress((void**)&p_em,  g_em);

    __nv_bfloat16 *offh, *offl, *shfh, *shfl, *e1h, *e1l;
    cudaGetSymbolAddress((void**)&offh, g_off_hi);
    cudaGetSymbolAddress((void**)&offl, g_off_lo);
    cudaGetSymbolAddress((void**)&shfh, g_shf_hi);
    cudaGetSymbolAddress((void**)&shfl, g_shf_lo);
    cudaGetSymbolAddress((void**)&e1h,  g_e1_hi);
    cudaGetSymbolAddress((void**)&e1l,  g_e1_lo);

    __nv_bfloat16 *whom, *wlom, *whe1, *wle1, *whe2, *wle2;
    cudaGetSymbolAddress((void**)&whom, g_wh_om);
    cudaGetSymbolAddress((void**)&wlom, g_wl_om);
    cudaGetSymbolAddress((void**)&whe1, g_wh_em1);
    cudaGetSymbolAddress((void**)&wle1, g_wl_em1);
    cudaGetSymbolAddress((void**)&whe2, g_wh_em2);
    cudaGetSymbolAddress((void**)&wle2, g_wl_em2);

    const int SM_OM  = 69632 + 2 * 2 * 216 * 144;  // 194048
    const int SM_EM1 = 69632 + 2 * 2 *  64 * 144;  // 106496
    const int SM_EM2 = 69632 + 2 * 2 *  72 * 144;  // 111104
    cudaFuncSetAttribute(conv_ps_kernel<64, 64, 216, 14, 0, 0>,
                         cudaFuncAttributeMaxDynamicSharedMemorySize, SM_OM);
    cudaFuncSetAttribute(conv_ps_kernel<128, 64, 64, 4, 1, 1>,
                         cudaFuncAttributeMaxDynamicSharedMemorySize, SM_EM1);
    cudaFuncSetAttribute(conv_ps_kernel<64, 64, 72, 5, 2, 0>,
                         cudaFuncAttributeMaxDynamicSharedMemorySize, SM_EM2);

    // pre-split weights + inputs
    wsplit2_kernel<<<(216 *  576 + 255) / 256, 256>>>(w_om,  whom, wlom, 216 *  576);
    wsplit2_kernel<<<( 64 * 1152 + 255) / 256, 256>>>(w_em1, whe1, wle1,  64 * 1152);
    wsplit2_kernel<<<( 72 *  576 + 255) / 256, 256>>>(w_em2, whe2, wle2,  72 *  576);
    psplit2_kernel<<<dim3(128, 512), 160>>>(off, offh, offl, shf, shfh, shfl);

    // om = conv3x3(offset_feat) : 64 -> 216
    conv_ps_kernel<64, 64, 216, 14, 0, 0><<<dim3(128, 4), 512, SM_OM>>>(
        offh, offl, offh, offl, whom, wlom, b_om, p_om);

    // em1 = leaky(conv3x3(concat(share, offset_feat))) : 128 -> 64
    // epilogue writes bf16 hi/lo shifted planes directly (no fp32, no psplit)
    conv_ps_kernel<128, 64, 64, 4, 1, 1><<<dim3(128, 4), 512, SM_EM1>>>(
        shfh, shfl, offh, offl, whe1, wle1, b_em1, p_em);

    // em = sigmoid(conv3x3(em1)) : 64 -> 72
    conv_ps_kernel<64, 64, 72, 5, 2, 0><<<dim3(128, 4), 512, SM_EM2>>>(
        e1h, e1l, e1h, e1l, whe2, wle2, b_em2, p_em);

    // both deformable convs fused (shared offsets + weights)
    deform_kernel<<<dim3(8, 8, 32), 256>>>(x, shf, w_dc, b_dc, out);
}

// round 16
// speedup vs baseline: 1.0387x; 1.0387x over previous
#include <cuda_runtime.h>
#include <cuda_bf16.h>
#include <math.h>
#include <stdint.h>

#define HW 16384
#define PLN (128 * 136)          // padded plane elems per (b,ci)

// fp32 scratch (module-load allocated, legal per harness rules)
__device__ float g_om [4 * 216 * HW];
__device__ float g_em1[4 *  64 * HW];
__device__ float g_em [4 *  72 * HW];

// Pre-split inputs: 3 kx-shifted zero-padded bf16 planes, hi & lo.
// layout [s][b*ci][h][136], row stride 272B (16B-aligned).
__device__ __nv_bfloat16 g_off_hi[3 * 4 * 64 * PLN];
__device__ __nv_bfloat16 g_off_lo[3 * 4 * 64 * PLN];
__device__ __nv_bfloat16 g_shf_hi[3 * 4 * 64 * PLN];
__device__ __nv_bfloat16 g_shf_lo[3 * 4 * 64 * PLN];
__device__ __nv_bfloat16 g_e1_hi [3 * 4 * 64 * PLN];
__device__ __nv_bfloat16 g_e1_lo [3 * 4 * 64 * PLN];

// Pre-split weights (separate hi/lo bf16, K-major [co][Cin*9])
__device__ __nv_bfloat16 g_wh_om [216 *  576];
__device__ __nv_bfloat16 g_wl_om [216 *  576];
__device__ __nv_bfloat16 g_wh_em1[ 64 * 1152];
__device__ __nv_bfloat16 g_wl_em1[ 64 * 1152];
__device__ __nv_bfloat16 g_wh_em2[ 72 *  576];
__device__ __nv_bfloat16 g_wl_em2[ 72 *  576];

// ---------------------------------------------------------------------------
__global__ void wsplit2_kernel(const float* __restrict__ w,
                               __nv_bfloat16* __restrict__ hi,
                               __nv_bfloat16* __restrict__ lo, int n)
{
    int i = blockIdx.x * 256 + threadIdx.x;
    if (i >= n) return;
    float x = w[i];
    __nv_bfloat16 h = __float2bfloat16(x);
    hi[i] = h;
    lo[i] = __float2bfloat16(x - __bfloat162float(h));
}

// presplit ONE input into 3 shifted padded bf16 hi/lo planes (R14-proven)
__global__ void psplit_kernel(const float* __restrict__ src,
                              __nv_bfloat16* __restrict__ hi,
                              __nv_bfloat16* __restrict__ lo, int nbc)
{
    int h = blockIdx.x, bc = blockIdx.y, m = threadIdx.x;
    if (m >= 136) return;
    const float* row = src + (size_t)bc * HW + h * 128;
    size_t S = (size_t)nbc * PLN;
#pragma unroll
    for (int s = 0; s < 3; s++) {
        int g = m - 1 + s;
        float v = (g >= 0 && g < 128) ? row[g] : 0.f;
        __nv_bfloat16 hv = __float2bfloat16(v);
        __nv_bfloat16 lv = __float2bfloat16(v - __bfloat162float(hv));
        size_t o = (size_t)s * S + ((size_t)bc * 128 + h) * 136 + m;
        hi[o] = hv;
        lo[o] = lv;
    }
}

// presplit TWO inputs (off, shf) in one launch (R15-verified: 38.4us vs 2x21)
__global__ void psplit2_kernel(const float* __restrict__ srcA,
                               __nv_bfloat16* __restrict__ hiA,
                               __nv_bfloat16* __restrict__ loA,
                               const float* __restrict__ srcB,
                               __nv_bfloat16* __restrict__ hiB,
                               __nv_bfloat16* __restrict__ loB)
{
    int h = blockIdx.x, bc = blockIdx.y, m = threadIdx.x;
    if (m >= 136) return;
    const float* src = srcA;
    __nv_bfloat16 *hi = hiA, *lo = loA;
    if (bc >= 256) { bc -= 256; src = srcB; hi = hiB; lo = loB; }
    const float* row = src + (size_t)bc * HW + h * 128;
    size_t S = (size_t)256 * PLN;
#pragma unroll
    for (int s = 0; s < 3; s++) {
        int g = m - 1 + s;
        float v = (g >= 0 && g < 128) ? row[g] : 0.f;
        __nv_bfloat16 hv = __float2bfloat16(v);
        __nv_bfloat16 lv = __float2bfloat16(v - __bfloat162float(hv));
        size_t o = (size_t)s * S + ((size_t)bc * 128 + h) * 136 + m;
        hi[o] = hv;
        lo[o] = lv;
    }
}

// ---------------------------------------------------------------------------
// warp-mma helpers (baseline PTX, valid at compute_103)
// ---------------------------------------------------------------------------
__device__ __forceinline__ void ldm_x4t(uint32_t* r, uint32_t addr) {
    asm volatile("ldmatrix.sync.aligned.m8n8.x4.trans.shared.b16 {%0,%1,%2,%3}, [%4];"
        : "=r"(r[0]), "=r"(r[1]), "=r"(r[2]), "=r"(r[3]) : "r"(addr));
}
__device__ __forceinline__ void ldm_x2(uint32_t* r, uint32_t addr) {
    asm volatile("ldmatrix.sync.aligned.m8n8.x2.shared.b16 {%0,%1}, [%2];"
        : "=r"(r[0]), "=r"(r[1]) : "r"(addr));
}
__device__ __forceinline__ void mma_bf16(float* c, const uint32_t* a, const uint32_t* b) {
    asm volatile("mma.sync.aligned.m16n8k16.row.col.f32.bf16.bf16.f32 "
        "{%0,%1,%2,%3},{%4,%5,%6,%7},{%8,%9},{%0,%1,%2,%3};"
        : "+f"(c[0]), "+f"(c[1]), "+f"(c[2]), "+f"(c[3])
        : "r"(a[0]), "r"(a[1]), "r"(a[2]), "r"(a[3]), "r"(b[0]), "r"(b[1]));
}

// ===========================================================================
// Implicit-GEMM conv3x3 on mma.sync bf16 3-pass, cp.async double-buffered.
// (R14-proven version, byte-identical compute path)
// ===========================================================================
template<int CIN, int CIN1, int COUT, int NTG0, int ACT>
__global__ __launch_bounds__(512, 1) void conv_ps_kernel(
    const __nv_bfloat16* __restrict__ p1hi, const __nv_bfloat16* __restrict__ p1lo,
    const __nv_bfloat16* __restrict__ p2hi, const __nv_bfloat16* __restrict__ p2lo,
    const __nv_bfloat16* __restrict__ whi,  const __nv_bfloat16* __restrict__ wlo,
    const float* __restrict__ bias, float* __restrict__ out)
{
    constexpr int K      = CIN * 9;
    constexpr int NCH    = K / 64;
    constexpr int NT_TOT = (COUT + 7) / 8;
    constexpr int CIN2   = CIN - CIN1;
    constexpr size_t S1  = (size_t)4 * CIN1 * PLN;
    constexpr size_t S2  = (size_t)4 * (CIN2 ? CIN2 : 1) * PLN;
    constexpr int ASZ    = 2 * 64 * 272;
    constexpr int BB     = 2 * ASZ;
    constexpr int BSZ    = 2 * COUT * 144;

    extern __shared__ char smem[];
    uint32_t sb;
    asm("{ .reg .u64 t; cvta.to.shared.u64 t, %1; cvt.u32.u64 %0, t; }"
        : "=r"(sb) : "l"(smem));

    const int tid  = threadIdx.x;
    const int lane = tid & 31;
    const int wid  = tid >> 5;
    const int h    = blockIdx.x;
    const int b    = blockIdx.y;

    const int mw = wid & 7;
    const int wg = wid >> 3;
    const int m0 = mw * 16;
    const int ntc = wg ? (NT_TOT - NTG0) : NTG0;
    const int ntb = wg * NTG0;

    float acc[NTG0][4];
#pragma unroll
    for (int nt = 0; nt < NTG0; nt++)
#pragma unroll
        for (int q = 0; q < 4; q++) acc[nt][q] = 0.f;

    const uint32_t a_k  = (uint32_t)(((lane >> 4) << 3) + (lane & 7));
    const uint32_t a_m  = (uint32_t)(m0 + (((lane >> 3) & 1) << 3));
    const uint32_t aoff = a_k * 272 + a_m * 2;
    const uint32_t boff = (uint32_t)((lane & 7) * 144 + ((lane >> 3) & 1) * 16);

    auto stage = [&](int kc, int buf) {
#pragma unroll
        for (int i = 0; i < 4; i++) {
            int idx = tid + 512 * i;
            int pl  = idx >> 10;
            int rem = idx & 1023;
            int kr  = rem >> 4;
            int ch  = rem & 15;
            int k  = kc * 64 + kr;
            int ci = k / 9, r = k - 9 * ci, ky = r / 3, kx = r - 3 * ky;
            int gh = h - 1 + ky;
            int sz = ((unsigned)gh < 128u) ? 16 : 0;
            int ghc = min(max(gh, 0), 127);
            const __nv_bfloat16* base;
            if (ci < CIN1)
                base = (pl ? p1lo : p1hi) + (size_t)kx * S1
                     + ((size_t)(b * CIN1 + ci) * 128 + ghc) * 136;
            else
                base = (pl ? p2lo : p2hi) + (size_t)kx * S2
                     + ((size_t)(b * CIN2 + (ci - CIN1)) * 128 + ghc) * 136;
            const char* src = (const char*)base + ch * 16;
            uint32_t dst = sb + buf * ASZ + pl * 17408 + kr * 272 + ch * 16;
            asm volatile("cp.async.cg.shared.global [%0], [%1], 16, %2;"
                         :: "r"(dst), "l"(src), "r"(sz));
        }
        for (int idx = tid; idx < COUT * 16; idx += 512) {
            int pl  = (idx >= COUT * 8) ? 1 : 0;
            int rem = idx - pl * COUT * 8;
            int co  = rem >> 3;
            int ch  = rem & 7;
            const __nv_bfloat16* w = pl ? wlo : whi;
            const char* src = (const char*)(w + (size_t)co * K + kc * 64) + ch * 16;
            uint32_t dst = sb + BB + buf * BSZ + pl * (COUT * 144) + co * 144 + ch * 16;
            asm volatile("cp.async.cg.shared.global [%0], [%1], 16, 16;"
                         :: "r"(dst), "l"(src));
        }
        asm volatile("cp.async.commit_group;" ::: "memory");
    };

    stage(0, 0);

    int buf = 0;
    for (int kc = 0; kc < NCH; kc++, buf ^= 1) {
        if (kc + 1 < NCH) {
            stage(kc + 1, buf ^ 1);
            asm volatile("cp.async.wait_group 1;" ::: "memory");
        } else {
            asm volatile("cp.async.wait_group 0;" ::: "memory");
        }
        __syncthreads();

        uint32_t Ab = sb + buf * ASZ;
        uint32_t Bb = sb + BB + buf * BSZ;
#pragma unroll
        for (int kt = 0; kt < 4; kt++) {
            uint32_t ah[4], al[4];
            ldm_x4t(ah, Ab + kt * 4352 + aoff);
            ldm_x4t(al, Ab + 17408 + kt * 4352 + aoff);
#pragma unroll
            for (int nt = 0; nt < NTG0; nt++) {
                if (nt < ntc) {
                    uint32_t bh[2], bl[2];
                    ldm_x2(bh, Bb + (ntb + nt) * 1152 + boff + kt * 32);
                    ldm_x2(bl, Bb + COUT * 144 + (ntb + nt) * 1152 + boff + kt * 32);
                    mma_bf16(acc[nt], ah, bh);
                    mma_bf16(acc[nt], ah, bl);
                    mma_bf16(acc[nt], al, bh);
                }
            }
        }
        __syncthreads();
    }

    // epilogue
    const int mA = m0 + (lane >> 2);
#pragma unroll
    for (int nt = 0; nt < NTG0; nt++) {
        if (nt < ntc) {
            int coA = (ntb + nt) * 8 + 2 * (lane & 3);
            float ba = bias[coA], bb = bias[coA + 1];
            float v[4] = { acc[nt][0] + ba, acc[nt][1] + bb,
                           acc[nt][2] + ba, acc[nt][3] + bb };
#pragma unroll
            for (int q = 0; q < 4; q++) {
                if (ACT == 1) v[q] = (v[q] >= 0.f) ? v[q] : 0.1f * v[q];
                if (ACT == 2) v[q] = 1.f / (1.f + expf(-v[q]));
            }
            size_t o00 = ((size_t)b * COUT + coA) * HW + h * 128 + mA;
            out[o00]          = v[0];
            out[o00 + HW]     = v[1];
            out[o00 + 8]      = v[2];
            out[o00 + HW + 8] = v[3];
        }
    }
}

// ---------------------------------------------------------------------------
// Fused dual modulated deformable conv (DCNv2), stride 1, pad 1. (unchanged)
// ---------------------------------------------------------------------------
__global__ __launch_bounds__(256) void deform_kernel(
    const float* __restrict__ x, const float* __restrict__ s,
    const float* __restrict__ w_dc, const float* __restrict__ b_dc,
    float* __restrict__ out)
{
    __shared__ float s_w[8][8][9];

    const int tid = threadIdx.x;
    const int b = blockIdx.z >> 3;
    const int g = blockIdx.z & 7;
    const int ty = tid >> 4;
    const int tx = tid & 15;
    const int h  = blockIdx.y * 16 + ty;
    const int wp = blockIdx.x * 16 + tx;

    for (int i = tid; i < 576; i += 256)
        ((float*)s_w)[i] = w_dc[(size_t)g * 576 + i];
    __syncthreads();

    const int pix = h * 128 + wp;
    const float* om_b = g_om + (size_t)b * 216 * HW;
    const float* em_b = g_em + (size_t)b * 72 * HW;
    const float* xb = x + ((size_t)b * 64 + g * 8) * HW;
    const float* sb = s + ((size_t)b * 64 + g * 8) * HW;

    float accx[8], accs[8];
#pragma unroll
    for (int o = 0; o < 8; o++) { accx[o] = 0.f; accs[o] = 0.f; }

    for (int kk = 0; kk < 9; kk++) {
        const int mch = g * 9 + kk;
        float dy   = om_b[(size_t)(2 * mch) * HW + pix];
        float dx   = om_b[(size_t)(2 * mch + 1) * HW + pix];
        float mraw = om_b[(size_t)(144 + mch) * HW + pix];
        float mx = 1.f / (1.f + expf(-mraw));
        float me = em_b[(size_t)mch * HW + pix];

        float py = (float)(h - 1 + kk / 3) + dy;
        float px = (float)(wp - 1 + kk % 3) + dx;
        float y0f = floorf(py), x0f = floorf(px);
        int y0 = (int)y0f, x0 = (int)x0f;
        float ly = py - y0f, lx = px - x0f;
        int y1 = y0 + 1, x1 = x0 + 1;

        float vy0 = (y0 >= 0 && y0 < 128) ? 1.f : 0.f;
        float vy1 = (y1 >= 0 && y1 < 128) ? 1.f : 0.f;
        float vx0 = (x0 >= 0 && x0 < 128) ? 1.f : 0.f;
        float vx1 = (x1 >= 0 && x1 < 128) ? 1.f : 0.f;

        float w00 = (1.f - ly) * (1.f - lx) * vy0 * vx0;
        float w01 = (1.f - ly) * lx         * vy0 * vx1;
        float w10 = ly * (1.f - lx)         * vy1 * vx0;
        float w11 = ly * lx                 * vy1 * vx1;

        int cy0 = min(max(y0, 0), 127), cy1 = min(max(y1, 0), 127);
        int cx0 = min(max(x0, 0), 127), cx1 = min(max(x1, 0), 127);
        int i00 = cy0 * 128 + cx0, i01 = cy0 * 128 + cx1;
        int i10 = cy1 * 128 + cx0, i11 = cy1 * 128 + cx1;

#pragma unroll
        for (int c = 0; c < 8; c++) {
            const float* xp = xb + (size_t)c * HW;
            const float* sp = sb + (size_t)c * HW;
            float vx = w00 * xp[i00] + w01 * xp[i01] + w10 * xp[i10] + w11 * xp[i11];
            float vs = w00 * sp[i00] + w01 * sp[i01] + w10 * sp[i10] + w11 * sp[i11];
            float ax  = vx * mx;
            float as_ = vs * me;
#pragma unroll
            for (int o = 0; o < 8; o++) {
                float wv = s_w[o][c][kk];
                accx[o] += ax * wv;
                accs[o] += as_ * wv;
            }
        }
    }

#pragma unroll
    for (int o = 0; o < 8; o++) {
        float bs = b_dc[g * 8 + o];
        size_t oidx = ((size_t)b * 64 + g * 8 + o) * HW + pix;
        out[oidx] = accx[o] + bs;
        out[(size_t)4 * 64 * HW + oidx] = accs[o] + bs;
    }
}

extern "C" void kernel_launch(void* const* d_in, const int* in_sizes, int n_in,
                              void* d_out, int out_size)
{
    const float* x     = (const float*)d_in[0];
    const float* shf   = (const float*)d_in[1];
    const float* off   = (const float*)d_in[2];
    const float* w_om  = (const float*)d_in[3];
    const float* b_om  = (const float*)d_in[4];
    const float* w_em1 = (const float*)d_in[5];
    const float* b_em1 = (const float*)d_in[6];
    const float* w_em2 = (const float*)d_in[7];
    const float* b_em2 = (const float*)d_in[8];
    const float* w_dc  = (const float*)d_in[9];
    const float* b_dc  = (const float*)d_in[10];
    float* out = (float*)d_out;

    float *p_om, *p_em1, *p_em;
    cudaGetSymbolAddress((void**)&p_om,  g_om);
    cudaGetSymbolAddress((void**)&p_em1, g_em1);
    cudaGetSymbolAddress((void**)&p_em,  g_em);

    __nv_bfloat16 *offh, *offl, *shfh, *shfl, *e1h, *e1l;
    cudaGetSymbolAddress((void**)&offh, g_off_hi);
    cudaGetSymbolAddress((void**)&offl, g_off_lo);
    cudaGetSymbolAddress((void**)&shfh, g_shf_hi);
    cudaGetSymbolAddress((void**)&shfl, g_shf_lo);
    cudaGetSymbolAddress((void**)&e1h,  g_e1_hi);
    cudaGetSymbolAddress((void**)&e1l,  g_e1_lo);

    __nv_bfloat16 *whom, *wlom, *whe1, *wle1, *whe2, *wle2;
    cudaGetSymbolAddress((void**)&whom, g_wh_om);
    cudaGetSymbolAddress((void**)&wlom, g_wl_om);
    cudaGetSymbolAddress((void**)&whe1, g_wh_em1);
    cudaGetSymbolAddress((void**)&wle1, g_wl_em1);
    cudaGetSymbolAddress((void**)&whe2, g_wh_em2);
    cudaGetSymbolAddress((void**)&wle2, g_wl_em2);

    const int SM_OM  = 69632 + 2 * 2 * 216 * 144;  // 194048
    const int SM_EM1 = 69632 + 2 * 2 *  64 * 144;  // 106496
    const int SM_EM2 = 69632 + 2 * 2 *  72 * 144;  // 111104
    cudaFuncSetAttribute(conv_ps_kernel<64, 64, 216, 14, 0>,
                         cudaFuncAttributeMaxDynamicSharedMemorySize, SM_OM);
    cudaFuncSetAttribute(conv_ps_kernel<128, 64, 64, 4, 1>,
                         cudaFuncAttributeMaxDynamicSharedMemorySize, SM_EM1);
    cudaFuncSetAttribute(conv_ps_kernel<64, 64, 72, 5, 2>,
                         cudaFuncAttributeMaxDynamicSharedMemorySize, SM_EM2);

    // pre-split weights + inputs (off/shf merged into one launch)
    wsplit2_kernel<<<(216 *  576 + 255) / 256, 256>>>(w_om,  whom, wlom, 216 *  576);
    wsplit2_kernel<<<( 64 * 1152 + 255) / 256, 256>>>(w_em1, whe1, wle1,  64 * 1152);
    wsplit2_kernel<<<( 72 *  576 + 255) / 256, 256>>>(w_em2, whe2, wle2,  72 *  576);
    psplit2_kernel<<<dim3(128, 512), 160>>>(off, offh, offl, shf, shfh, shfl);

    // om = conv3x3(offset_feat) : 64 -> 216
    conv_ps_kernel<64, 64, 216, 14, 0><<<dim3(128, 4), 512, SM_OM>>>(
        offh, offl, offh, offl, whom, wlom, b_om, p_om);

    // em1 = leaky(conv3x3(concat(share, offset_feat))) : 128 -> 64
    conv_ps_kernel<128, 64, 64, 4, 1><<<dim3(128, 4), 512, SM_EM1>>>(
        shfh, shfl, offh, offl, whe1, wle1, b_em1, p_em1);

    // presplit em1 output (R14-proven separate kernel), then em2
    psplit_kernel<<<dim3(128, 256), 160>>>(p_em1, e1h, e1l, 256);

    // em = sigmoid(conv3x3(em1)) : 64 -> 72
    conv_ps_kernel<64, 64, 72, 5, 2><<<dim3(128, 4), 512, SM_EM2>>>(
        e1h, e1l, e1h, e1l, whe2, wle2, b_em2, p_em);

    // both deformable convs fused (shared offsets + weights)
    deform_kernel<<<dim3(8, 8, 32), 256>>>(x, shf, w_dc, b_dc, out);
}